// round 9
// baseline (speedup 1.0000x reference)
#include <cuda_runtime.h>
#include <cstdint>

// ---------------- problem constants ----------------
#define M_DIM 8192
#define K_DIM 4096
#define N_DIM 11008
#define NZ_DIM 1376
#define GS 128

// ---------------- GEMM tile config ----------------
#define BM 128
#define BN 128
#define BK 32                 // 128B rows (SW128 atom)
#define NSTAGES (K_DIM / BK)  // 128
#define SPIPE 3
#define GRPM 16

#define A_STAGE_BYTES (BM * 128)   // 16384
#define B_STAGE_BYTES (BN * 128)   // 16384
#define STAGE_BYTES (A_STAGE_BYTES + B_STAGE_BYTES)
#define SMEM_TOTAL (SPIPE * STAGE_BYTES)   // 98304 -> 2 CTAs/SM

#define MTILES (M_DIM / BM)   // 64
#define NTILES (N_DIM / BN)   // 86

// ---------------- scratch ----------------
__device__ float g_wt[(size_t)N_DIM * K_DIM];   // dequant W^T tf32: [N, K]
__device__ float g_ax[(size_t)M_DIM * K_DIM];   // x tf32: [M, K]

// ---------------- helpers ----------------
__device__ __forceinline__ uint32_t f2tf32(float f) {
    uint32_t r; asm("cvt.rna.tf32.f32 %0, %1;" : "=r"(r) : "f"(f)); return r;
}
__device__ __forceinline__ void cp16(uint32_t saddr, const float* g) {
    asm volatile("cp.async.cg.shared.global [%0], [%1], 16;" :: "r"(saddr), "l"(g));
}
__device__ __forceinline__ void cp_commit() { asm volatile("cp.async.commit_group;" ::: "memory"); }
__device__ __forceinline__ void cp_wait2()  { asm volatile("cp.async.wait_group 2;" ::: "memory"); }
__device__ __forceinline__ uint32_t smem_u32(const void* p) {
    uint32_t a;
    asm("{ .reg .u64 t; cvta.to.shared.u64 t, %1; cvt.u32.u64 %0, t; }" : "=r"(a) : "l"(p));
    return a;
}

// ---------------- prep: round x to tf32 (coalesced) ----------------
extern "C" __global__ void round_a_kernel(const float4* __restrict__ x) {
    size_t i = (size_t)blockIdx.x * blockDim.x + threadIdx.x;
    float4 v = x[i];
    float4 r;
    r.x = __uint_as_float(f2tf32(v.x));
    r.y = __uint_as_float(f2tf32(v.y));
    r.z = __uint_as_float(f2tf32(v.z));
    r.w = __uint_as_float(f2tf32(v.w));
    ((float4*)g_ax)[i] = r;
}

// ---------------- prep: dequant + transpose W -> tf32 [N, K] (coalesced) ----------------
extern "C" __global__ void dequant_wt_kernel(const uint32_t* __restrict__ qweight,
                                             const float* __restrict__ scales,
                                             const uint32_t* __restrict__ qzeros) {
    int n  = blockIdx.x * blockDim.x + threadIdx.x;   // 0..11007
    int kp = blockIdx.y;                              // 0..511
    int g  = kp >> 4;
    uint32_t q  = qweight[(size_t)kp * N_DIM + n];
    float    s  = scales[(size_t)g * N_DIM + n];
    uint32_t zq = qzeros[(size_t)g * NZ_DIM + (n >> 3)];
    float    sz = s * (float)((zq >> ((n & 7) * 4)) & 0xF);
    float w[8];
    #pragma unroll
    for (int j = 0; j < 8; j++)
        w[j] = __uint_as_float(f2tf32(fmaf(s, (float)((q >> (4 * j)) & 0xF), -sz)));
    float4* dst = (float4*)(g_wt + (size_t)n * K_DIM + kp * 8);
    dst[0] = make_float4(w[0], w[1], w[2], w[3]);
    dst[1] = make_float4(w[4], w[5], w[6], w[7]);
}

// ---------------- main GEMM: tf32 mma.sync, 128x128 CTA, occ=2 ----------------
extern "C" __global__ void __launch_bounds__(256, 2)
qgemm_tf32(float* __restrict__ out) {
    extern __shared__ char smem[];
    uint32_t sb = smem_u32(smem);

    const int t = threadIdx.x;
    const int warp = t >> 5, lane = t & 31;
    const int g8 = lane >> 2, tg = lane & 3;
    const int warp_m = warp >> 2;    // 0..1 -> 64 rows
    const int warp_n = warp & 3;     // 0..3 -> 32 cols

    const int bid   = blockIdx.x;
    const int group = bid / (GRPM * NTILES);
    const int rem   = bid % (GRPM * NTILES);
    const int m0    = (group * GRPM + (rem % GRPM)) * BM;
    const int n0    = (rem / GRPM) * BN;

    float c[4][4][4];
    #pragma unroll
    for (int i = 0; i < 4; i++)
        #pragma unroll
        for (int j = 0; j < 4; j++)
            #pragma unroll
            for (int k = 0; k < 4; k++) c[i][j][k] = 0.f;

    // ---- cp.async addresses (SW128 swizzle on 128B rows); 4 A + 4 B granules/thread ----
    const float* a_g[4]; uint32_t a_s[4];
    const float* b_g[4]; uint32_t b_s[4];
    #pragma unroll
    for (int i = 0; i < 4; i++) {
        int idx = t + i * 256;            // 0..1023
        int r = idx >> 3, g = idx & 7;    // row 0..127, granule 0..7
        uint32_t so = r * 128 + ((g ^ (r & 7)) << 4);
        a_g[i] = g_ax + (size_t)(m0 + r) * K_DIM + g * 4;
        a_s[i] = sb + so;
        b_g[i] = g_wt + (size_t)(n0 + r) * K_DIM + g * 4;
        b_s[i] = sb + A_STAGE_BYTES + so;
    }

    auto fill = [&](int s) {
        int off = (s % SPIPE) * STAGE_BYTES;
        #pragma unroll
        for (int i = 0; i < 4; i++) cp16(a_s[i] + off, a_g[i] + s * BK);
        #pragma unroll
        for (int i = 0; i < 4; i++) cp16(b_s[i] + off, b_g[i] + s * BK);
        cp_commit();
    };

    fill(0); fill(1);

    const int axor = g8 << 2;

    for (int s = 0; s < NSTAGES; s++) {
        if (s + 2 < NSTAGES) fill(s + 2); else cp_commit();
        cp_wait2();
        __syncthreads();

        const uint32_t* A = (const uint32_t*)(smem + (s % SPIPE) * STAGE_BYTES);
        const uint32_t* B = A + A_STAGE_BYTES / 4;

        #pragma unroll
        for (int kk = 0; kk < BK; kk += 8) {
            uint32_t af[4][4];
            #pragma unroll
            for (int mi = 0; mi < 4; mi++) {
                int r = warp_m * 64 + mi * 16 + g8;
                const uint32_t* ap = A + r * 32;
                af[mi][0] = ap[(kk + tg) ^ axor];
                af[mi][1] = ap[8 * 32 + ((kk + tg) ^ axor)];
                af[mi][2] = ap[(kk + 4 + tg) ^ axor];
                af[mi][3] = ap[8 * 32 + ((kk + 4 + tg) ^ axor)];
            }
            uint32_t bf[4][2];
            #pragma unroll
            for (int ni = 0; ni < 4; ni++) {
                int r = warp_n * 32 + ni * 8 + g8;
                const uint32_t* bp = B + r * 32;
                bf[ni][0] = bp[(kk + tg) ^ axor];
                bf[ni][1] = bp[(kk + 4 + tg) ^ axor];
            }
            #pragma unroll
            for (int mi = 0; mi < 4; mi++)
                #pragma unroll
                for (int ni = 0; ni < 4; ni++) {
                    asm volatile(
                        "mma.sync.aligned.m16n8k8.row.col.f32.tf32.tf32.f32 "
                        "{%0,%1,%2,%3}, {%4,%5,%6,%7}, {%8,%9}, {%0,%1,%2,%3};"
                        : "+f"(c[mi][ni][0]), "+f"(c[mi][ni][1]),
                          "+f"(c[mi][ni][2]), "+f"(c[mi][ni][3])
                        : "r"(af[mi][0]), "r"(af[mi][1]), "r"(af[mi][2]), "r"(af[mi][3]),
                          "r"(bf[ni][0]), "r"(bf[ni][1]));
                }
        }
        __syncthreads();   // SPIPE=3: protect buf s from fill(s+3) by fast warps
    }

    // ---- epilogue ----
    #pragma unroll
    for (int mi = 0; mi < 4; mi++) {
        int row = m0 + warp_m * 64 + mi * 16 + g8;
        float* o0 = out + (size_t)row * N_DIM;
        float* o1 = out + (size_t)(row + 8) * N_DIM;
        #pragma unroll
        for (int ni = 0; ni < 4; ni++) {
            int col = n0 + warp_n * 32 + ni * 8 + 2 * tg;
            *(float2*)(o0 + col) = make_float2(c[mi][ni][0], c[mi][ni][1]);
            *(float2*)(o1 + col) = make_float2(c[mi][ni][2], c[mi][ni][3]);
        }
    }
}

// ---------------- launch ----------------
extern "C" void kernel_launch(void* const* d_in, const int* in_sizes, int n_in,
                              void* d_out, int out_size) {
    const float*    x       = (const float*)d_in[0];
    const uint32_t* qweight = (const uint32_t*)d_in[1];
    const float*    scales  = (const float*)d_in[2];
    const uint32_t* qzeros  = (const uint32_t*)d_in[3];
    float*          out     = (float*)d_out;

    cudaFuncSetAttribute(qgemm_tf32,
                         cudaFuncAttributeMaxDynamicSharedMemorySize, SMEM_TOTAL);

    round_a_kernel<<<(unsigned)((size_t)M_DIM * K_DIM / 4 / 256), 256>>>((const float4*)x);
    dim3 dq_grid(N_DIM / 256, K_DIM / 8);   // (43, 512)
    dequant_wt_kernel<<<dq_grid, 256>>>(qweight, scales, qzeros);
    qgemm_tf32<<<MTILES * NTILES, 256, SMEM_TOTAL>>>(out);   // 5504 CTAs
}

// round 10
// speedup vs baseline: 2.0528x; 2.0528x over previous
#include <cuda_runtime.h>
#include <cuda_fp16.h>
#include <cstdint>

// ---------------- problem constants ----------------
#define M_DIM 8192
#define K_DIM 4096
#define N_DIM 11008
#define NZ_DIM 1376
#define GS 128

// ---------------- GEMM tile config ----------------
#define BM 128
#define BN 256
#define BK 64                 // 64 halves -> 128B rows (SW128 atom)
#define NSTAGES (K_DIM / BK)  // 64
#define SPIPE 4
#define GRPM 8

#define A_STAGE_BYTES (BM * 128)   // 16384
#define B_STAGE_BYTES (BN * 128)   // 32768
#define STAGE_BYTES (A_STAGE_BYTES + B_STAGE_BYTES)
#define SMEM_TOTAL (SPIPE * STAGE_BYTES)   // 196608

#define MTILES (M_DIM / BM)   // 64
#define NTILES (N_DIM / BN)   // 43

// ---------------- scratch ----------------
__device__ __half g_wt[(size_t)N_DIM * K_DIM];   // dequant W^T fp16: [N, K]
__device__ __half g_ax[(size_t)M_DIM * K_DIM];   // x fp16: [M, K]

// ---------------- helpers ----------------
__device__ __forceinline__ void cp16(uint32_t saddr, const void* g) {
    asm volatile("cp.async.cg.shared.global [%0], [%1], 16;" :: "r"(saddr), "l"(g));
}
__device__ __forceinline__ void cp_commit() { asm volatile("cp.async.commit_group;" ::: "memory"); }
__device__ __forceinline__ void cp_wait3()  { asm volatile("cp.async.wait_group 3;" ::: "memory"); }
__device__ __forceinline__ uint32_t smem_u32(const void* p) {
    uint32_t a;
    asm("{ .reg .u64 t; cvta.to.shared.u64 t, %1; cvt.u32.u64 %0, t; }" : "=r"(a) : "l"(p));
    return a;
}

// ---------------- prep: x -> fp16 (coalesced, 8 floats -> 16B per thread) ----------------
extern "C" __global__ void round_a_kernel(const float4* __restrict__ x) {
    size_t i = (size_t)blockIdx.x * blockDim.x + threadIdx.x;
    float4 v0 = x[2 * i];
    float4 v1 = x[2 * i + 1];
    __half2 h[4];
    h[0] = __float22half2_rn(make_float2(v0.x, v0.y));
    h[1] = __float22half2_rn(make_float2(v0.z, v0.w));
    h[2] = __float22half2_rn(make_float2(v1.x, v1.y));
    h[3] = __float22half2_rn(make_float2(v1.z, v1.w));
    ((uint4*)g_ax)[i] = *(uint4*)h;
}

// ---------------- prep: dequant + transpose W -> fp16 [N, K] ----------------
extern "C" __global__ void dequant_wt_kernel(const uint32_t* __restrict__ qweight,
                                             const float* __restrict__ scales,
                                             const uint32_t* __restrict__ qzeros) {
    int n  = blockIdx.x * blockDim.x + threadIdx.x;   // 0..11007
    int kp = blockIdx.y;                              // 0..511 packed k-row (8 k each)
    int g  = kp >> 4;
    uint32_t q  = qweight[(size_t)kp * N_DIM + n];
    float    s  = scales[(size_t)g * N_DIM + n];
    uint32_t zq = qzeros[(size_t)g * NZ_DIM + (n >> 3)];
    float    sz = s * (float)((zq >> ((n & 7) * 4)) & 0xF);
    __half2 h[4];
    #pragma unroll
    for (int j = 0; j < 4; j++) {
        float w0 = fmaf(s, (float)((q >> (8 * j))     & 0xF), -sz);
        float w1 = fmaf(s, (float)((q >> (8 * j + 4)) & 0xF), -sz);
        h[j] = __float22half2_rn(make_float2(w0, w1));
    }
    *(uint4*)(g_wt + (size_t)n * K_DIM + kp * 8) = *(uint4*)h;
}

// ---------------- main GEMM: fp16 mma.sync m16n8k16, 128x256 CTA, 64x64 warp ----------------
extern "C" __global__ void __launch_bounds__(256, 1)
qgemm_f16(float* __restrict__ out) {
    extern __shared__ char smem[];
    uint32_t sb = smem_u32(smem);

    const int t = threadIdx.x;
    const int warp = t >> 5, lane = t & 31;
    const int g8 = lane >> 2, tg = lane & 3;
    const int warp_m = warp >> 2;    // 0..1 -> 64 rows
    const int warp_n = warp & 3;     // 0..3 -> 64 cols

    const int bid   = blockIdx.x;
    const int group = bid / (GRPM * NTILES);
    const int rem   = bid % (GRPM * NTILES);
    const int m0    = (group * GRPM + (rem % GRPM)) * BM;
    const int n0    = (rem / GRPM) * BN;

    float c[4][8][4];
    #pragma unroll
    for (int i = 0; i < 4; i++)
        #pragma unroll
        for (int j = 0; j < 8; j++)
            #pragma unroll
            for (int k = 0; k < 4; k++) c[i][j][k] = 0.f;

    // ---- cp.async addresses (SW128 swizzle on 128B rows; granule = 16B = 8 halves) ----
    const __half* a_g[4]; uint32_t a_s[4];
    #pragma unroll
    for (int i = 0; i < 4; i++) {
        int idx = t + i * 256;            // 0..1023
        int r = idx >> 3, g = idx & 7;
        a_g[i] = g_ax + (size_t)(m0 + r) * K_DIM + g * 8;
        a_s[i] = sb + r * 128 + ((g ^ (r & 7)) << 4);
    }
    const __half* b_g[8]; uint32_t b_s[8];
    #pragma unroll
    for (int i = 0; i < 8; i++) {
        int idx = t + i * 256;            // 0..2047
        int r = idx >> 3, g = idx & 7;
        b_g[i] = g_wt + (size_t)(n0 + r) * K_DIM + g * 8;
        b_s[i] = sb + A_STAGE_BYTES + r * 128 + ((g ^ (r & 7)) << 4);
    }

    auto fill = [&](int s) {
        int off = (s & (SPIPE - 1)) * STAGE_BYTES;
        #pragma unroll
        for (int i = 0; i < 4; i++) cp16(a_s[i] + off, a_g[i] + s * BK);
        #pragma unroll
        for (int i = 0; i < 8; i++) cp16(b_s[i] + off, b_g[i] + s * BK);
        cp_commit();
    };

    fill(0); fill(1); fill(2);

    for (int s = 0; s < NSTAGES; s++) {
        if (s + 3 < NSTAGES) fill(s + 3); else cp_commit();
        cp_wait3();
        __syncthreads();    // single barrier: SPIPE=4 keeps max skew (1 stage) safe

        const uint32_t* A = (const uint32_t*)(smem + (s & (SPIPE - 1)) * STAGE_BYTES);
        const uint32_t* B = A + A_STAGE_BYTES / 4;

        #pragma unroll
        for (int kb = 0; kb < 4; kb++) {           // k16 blocks; granule base gb = 2*kb
            const int gb = kb * 2;
            uint32_t af[4][4];
            #pragma unroll
            for (int mi = 0; mi < 4; mi++) {
                int r = warp_m * 64 + mi * 16 + g8;    // r&7 == g8
                const uint32_t* ap0 = A + r * 32;
                const uint32_t* ap1 = A + (r + 8) * 32;
                int w0 = ((gb ^ g8) << 2) + tg;
                int w1 = (((gb + 1) ^ g8) << 2) + tg;
                af[mi][0] = ap0[w0];   // (g8,    k=2tg..2tg+1)
                af[mi][1] = ap1[w0];   // (g8+8,  k=2tg..2tg+1)
                af[mi][2] = ap0[w1];   // (g8,    k=2tg+8..9)
                af[mi][3] = ap1[w1];   // (g8+8,  k=2tg+8..9)
            }
            uint32_t bf[8][2];
            #pragma unroll
            for (int ni = 0; ni < 8; ni++) {
                int r = warp_n * 64 + ni * 8 + g8;     // r&7 == g8
                const uint32_t* bp = B + r * 32;
                bf[ni][0] = bp[((gb ^ g8) << 2) + tg];
                bf[ni][1] = bp[(((gb + 1) ^ g8) << 2) + tg];
            }
            #pragma unroll
            for (int mi = 0; mi < 4; mi++)
                #pragma unroll
                for (int ni = 0; ni < 8; ni++) {
                    asm volatile(
                        "mma.sync.aligned.m16n8k16.row.col.f32.f16.f16.f32 "
                        "{%0,%1,%2,%3}, {%4,%5,%6,%7}, {%8,%9}, {%0,%1,%2,%3};"
                        : "+f"(c[mi][ni][0]), "+f"(c[mi][ni][1]),
                          "+f"(c[mi][ni][2]), "+f"(c[mi][ni][3])
                        : "r"(af[mi][0]), "r"(af[mi][1]), "r"(af[mi][2]), "r"(af[mi][3]),
                          "r"(bf[ni][0]), "r"(bf[ni][1]));
                }
        }
    }

    // ---- epilogue ----
    #pragma unroll
    for (int mi = 0; mi < 4; mi++) {
        int row = m0 + warp_m * 64 + mi * 16 + g8;
        float* o0 = out + (size_t)row * N_DIM;
        float* o1 = out + (size_t)(row + 8) * N_DIM;
        #pragma unroll
        for (int ni = 0; ni < 8; ni++) {
            int col = n0 + warp_n * 64 + ni * 8 + 2 * tg;
            *(float2*)(o0 + col) = make_float2(c[mi][ni][0], c[mi][ni][1]);
            *(float2*)(o1 + col) = make_float2(c[mi][ni][2], c[mi][ni][3]);
        }
    }
}

// ---------------- launch ----------------
extern "C" void kernel_launch(void* const* d_in, const int* in_sizes, int n_in,
                              void* d_out, int out_size) {
    const float*    x       = (const float*)d_in[0];
    const uint32_t* qweight = (const uint32_t*)d_in[1];
    const float*    scales  = (const float*)d_in[2];
    const uint32_t* qzeros  = (const uint32_t*)d_in[3];
    float*          out     = (float*)d_out;

    cudaFuncSetAttribute(qgemm_f16,
                         cudaFuncAttributeMaxDynamicSharedMemorySize, SMEM_TOTAL);

    round_a_kernel<<<(unsigned)((size_t)M_DIM * K_DIM / 8 / 256), 256>>>((const float4*)x);
    dim3 dq_grid(N_DIM / 256, K_DIM / 8);   // (43, 512)
    dequant_wt_kernel<<<dq_grid, 256>>>(qweight, scales, qzeros);
    qgemm_f16<<<MTILES * NTILES, 256, SMEM_TOTAL>>>(out);
}